// round 4
// baseline (speedup 1.0000x reference)
#include <cuda_runtime.h>
#include <cstdint>

#define NND 100000
#define NED 3200000
#define IN_DIM 128
#define HID 64
#define NCLS 8

// ---- scratch layout (floats) in one __device__ buffer -----------------------
// [0      , 100000 ) out_deg
// [100000 , 200000 ) in_deg
// [200000 , 6600000) agg1   (N x 64)
// [6600000, 7400000) agg2   (N x 8)
//   ^^^ first 7,400,000 floats zeroed each run
// [7400000,13800000) h_proj (N x 64)
// [13800000,14600000) h2_proj(N x 8)
// [14600000,14700000) out_norm
// [14700000,14800000) in_norm
#define OFF_OUTDEG 0
#define OFF_INDEG  100000
#define OFF_AGG1   200000
#define OFF_AGG2   6600000
#define ZERO_FLOATS 7400000
#define OFF_HPROJ  7400000
#define OFF_H2     13800000
#define OFF_ONORM  14600000
#define OFF_INORM  14700000
#define TOTAL_FLOATS 14800000

__device__ float4 g_buf4[TOTAL_FLOATS / 4];

__device__ __forceinline__ void red_add_v4(float4* addr, float4 v) {
    asm volatile("red.global.add.v4.f32 [%0], {%1, %2, %3, %4};"
                 :: "l"(addr), "f"(v.x), "f"(v.y), "f"(v.z), "f"(v.w)
                 : "memory");
}

// ---- zero the accumulation regions -----------------------------------------
__global__ void k_zero() {
    int i = blockIdx.x * blockDim.x + threadIdx.x;
    if (i < ZERO_FLOATS / 4) g_buf4[i] = make_float4(0.f, 0.f, 0.f, 0.f);
}

// ---- degree accumulation ----------------------------------------------------
__global__ void k_degree(const int* __restrict__ src, const int* __restrict__ dst) {
    int e = blockIdx.x * blockDim.x + threadIdx.x;
    if (e < NED) {
        float* buf = (float*)g_buf4;
        atomicAdd(buf + OFF_OUTDEG + src[e], 1.0f);
        atomicAdd(buf + OFF_INDEG  + dst[e], 1.0f);
    }
}

// ---- norms -------------------------------------------------------------------
__global__ void k_norm() {
    int n = blockIdx.x * blockDim.x + threadIdx.x;
    if (n < NND) {
        float* buf = (float*)g_buf4;
        buf[OFF_ONORM + n] = rsqrtf(fmaxf(buf[OFF_OUTDEG + n], 1.0f));
        buf[OFF_INORM + n] = rsqrtf(fmaxf(buf[OFF_INDEG  + n], 1.0f));
    }
}

// ---- GEMM1: h_proj[n][c] = sum_k x[n][k]*out_norm[n] * W1[k][c] --------------
// tile: 64 nodes x 64 cols, K chunked by 64. 256 threads = 16 nodegrp x 16 colgrp,
// each thread 4 nodes x 4 cols via float4 LDS.
__global__ void __launch_bounds__(256) k_gemm1(const float* __restrict__ x,
                                               const float* __restrict__ W1) {
    __shared__ float xs[64][68];   // [k][node], padded
    __shared__ float ws[64][64];   // [k][col]
    float* buf = (float*)g_buf4;
    const float* onorm = buf + OFF_ONORM;
    float* hproj = buf + OFF_HPROJ;

    int t  = threadIdx.x;
    int nb = blockIdx.x * 64;
    int ng = t & 15;   // node group: nodes ng*4 .. ng*4+3
    int cg = t >> 4;   // col group:  cols  cg*4 .. cg*4+3

    // x loading role: thread owns node ln, quarter lq (k = lq*16 .. lq*16+15)
    int ln = t >> 2;
    int lq = t & 3;
    int gn = nb + ln;
    float nrm = (gn < NND) ? onorm[gn] : 0.0f;

    float acc[4][4] = {};

    for (int kc = 0; kc < 2; kc++) {
        // load W1 chunk (64x64 floats = 1024 float4, linear, coalesced)
        const float4* W4 = (const float4*)(W1 + kc * 64 * 64);
        #pragma unroll
        for (int i = 0; i < 4; i++) {
            int lin = t + i * 256;
            ((float4*)ws)[lin] = W4[lin];
        }
        // load x chunk, transposed + scaled by out_norm
        #pragma unroll
        for (int i = 0; i < 4; i++) {
            float4 v = make_float4(0.f, 0.f, 0.f, 0.f);
            if (gn < NND)
                v = ((const float4*)(x + (size_t)gn * IN_DIM + kc * 64))[lq * 4 + i];
            int k0 = lq * 16 + i * 4;
            xs[k0 + 0][ln] = v.x * nrm;
            xs[k0 + 1][ln] = v.y * nrm;
            xs[k0 + 2][ln] = v.z * nrm;
            xs[k0 + 3][ln] = v.w * nrm;
        }
        __syncthreads();
        #pragma unroll 8
        for (int k = 0; k < 64; k++) {
            float4 xv = *(const float4*)&xs[k][ng * 4];
            float4 wv = *(const float4*)&ws[k][cg * 4];
            acc[0][0] += xv.x * wv.x; acc[0][1] += xv.x * wv.y;
            acc[0][2] += xv.x * wv.z; acc[0][3] += xv.x * wv.w;
            acc[1][0] += xv.y * wv.x; acc[1][1] += xv.y * wv.y;
            acc[1][2] += xv.y * wv.z; acc[1][3] += xv.y * wv.w;
            acc[2][0] += xv.z * wv.x; acc[2][1] += xv.z * wv.y;
            acc[2][2] += xv.z * wv.z; acc[2][3] += xv.z * wv.w;
            acc[3][0] += xv.w * wv.x; acc[3][1] += xv.w * wv.y;
            acc[3][2] += xv.w * wv.z; acc[3][3] += xv.w * wv.w;
        }
        __syncthreads();
    }

    #pragma unroll
    for (int i = 0; i < 4; i++) {
        int node = nb + ng * 4 + i;
        if (node < NND) {
            float4 o = make_float4(acc[i][0], acc[i][1], acc[i][2], acc[i][3]);
            ((float4*)(hproj + (size_t)node * HID))[cg] = o;
        }
    }
}

// ---- scatter layer 1: agg1[dst] += h_proj[src], 64 wide ----------------------
// 16 threads per edge, one float4 each; vector reduction into L2.
__global__ void __launch_bounds__(256) k_scatter1(const int* __restrict__ src,
                                                  const int* __restrict__ dst) {
    int i = blockIdx.x * 256 + threadIdx.x;   // 0 .. E*16-1 (exact grid)
    int e = i >> 4;
    int j = i & 15;
    int s = __ldg(src + e);
    int d = __ldg(dst + e);
    float* buf = (float*)g_buf4;
    const float4* hp = (const float4*)(buf + OFF_HPROJ);
    float4*       ag = (float4*)(buf + OFF_AGG1);
    float4 v = __ldg(&hp[(size_t)s * 16 + j]);
    red_add_v4(&ag[(size_t)d * 16 + j], v);
}

// ---- fused: relu(agg1*in_norm + b1) * out_norm  @ W2  -> h2_proj --------------
__global__ void __launch_bounds__(256) k_layer2(const float* __restrict__ W2,
                                                const float* __restrict__ b1) {
    __shared__ float w2s[64][8];
    __shared__ float b1s[64];
    int t = threadIdx.x;
    ((float*)w2s)[t]       = W2[t];
    ((float*)w2s)[t + 256] = W2[t + 256];
    if (t < 64) b1s[t] = b1[t];
    __syncthreads();

    int n = blockIdx.x * 256 + t;
    if (n >= NND) return;
    float* buf = (float*)g_buf4;
    float inr = buf[OFF_INORM + n];
    float onr = buf[OFF_ONORM + n];

    float acc[8] = {};
    const float4* a4 = (const float4*)(buf + OFF_AGG1 + (size_t)n * 64);
    #pragma unroll
    for (int q = 0; q < 16; q++) {
        float4 v = __ldg(&a4[q]);
        float vv[4] = {v.x, v.y, v.z, v.w};
        int k0 = q * 4;
        #pragma unroll
        for (int u = 0; u < 4; u++) {
            float h = fmaxf(fmaf(vv[u], inr, b1s[k0 + u]), 0.0f) * onr;
            #pragma unroll
            for (int j = 0; j < 8; j++) acc[j] = fmaf(h, w2s[k0 + u][j], acc[j]);
        }
    }
    float4* o4 = (float4*)(buf + OFF_H2 + (size_t)n * 8);
    o4[0] = make_float4(acc[0], acc[1], acc[2], acc[3]);
    o4[1] = make_float4(acc[4], acc[5], acc[6], acc[7]);
}

// ---- scatter layer 2: agg2[dst] += h2_proj[src], 8 wide -----------------------
__global__ void __launch_bounds__(256) k_scatter2(const int* __restrict__ src,
                                                  const int* __restrict__ dst) {
    int i = blockIdx.x * 256 + threadIdx.x;   // 0 .. E*2-1 (exact grid)
    int e = i >> 1;
    int j = i & 1;
    int s = __ldg(src + e);
    int d = __ldg(dst + e);
    float* buf = (float*)g_buf4;
    const float4* hp = (const float4*)(buf + OFF_H2);
    float4*       ag = (float4*)(buf + OFF_AGG2);
    float4 v = __ldg(&hp[(size_t)s * 2 + j]);
    red_add_v4(&ag[(size_t)d * 2 + j], v);
}

// ---- final: softmax(agg2*in_norm + b2) ----------------------------------------
__global__ void __launch_bounds__(256) k_softmax(const float* __restrict__ b2,
                                                 float* __restrict__ out) {
    int n = blockIdx.x * 256 + threadIdx.x;
    if (n >= NND) return;
    float* buf = (float*)g_buf4;
    float inr = buf[OFF_INORM + n];
    const float4* a4 = (const float4*)(buf + OFF_AGG2 + (size_t)n * 8);
    float4 a = a4[0], b = a4[1];
    float v[8] = {a.x, a.y, a.z, a.w, b.x, b.y, b.z, b.w};
    float m = -1e30f;
    #pragma unroll
    for (int j = 0; j < 8; j++) { v[j] = fmaf(v[j], inr, b2[j]); m = fmaxf(m, v[j]); }
    float s = 0.f;
    #pragma unroll
    for (int j = 0; j < 8; j++) { v[j] = __expf(v[j] - m); s += v[j]; }
    float rs = 1.0f / s;
    float4* o4 = (float4*)(out + (size_t)n * 8);
    o4[0] = make_float4(v[0] * rs, v[1] * rs, v[2] * rs, v[3] * rs);
    o4[1] = make_float4(v[4] * rs, v[5] * rs, v[6] * rs, v[7] * rs);
}

extern "C" void kernel_launch(void* const* d_in, const int* in_sizes, int n_in,
                              void* d_out, int out_size) {
    const float* x   = (const float*)d_in[0];
    const int*   src = (const int*)  d_in[1];
    const int*   dst = (const int*)  d_in[2];
    const float* W1  = (const float*)d_in[3];
    const float* b1  = (const float*)d_in[4];
    const float* W2  = (const float*)d_in[5];
    const float* b2  = (const float*)d_in[6];
    float* out = (float*)d_out;

    k_zero<<<(ZERO_FLOATS / 4 + 255) / 256, 256>>>();
    k_degree<<<NED / 256, 256>>>(src, dst);                 // 12500 blocks exact
    k_norm<<<(NND + 255) / 256, 256>>>();
    k_gemm1<<<(NND + 63) / 64, 256>>>(x, W1);
    k_scatter1<<<(NED * 16) / 256, 256>>>(src, dst);        // 200000 blocks exact
    k_layer2<<<(NND + 255) / 256, 256>>>(W2, b1);
    k_scatter2<<<(NED * 2) / 256, 256>>>(src, dst);         // 25000 blocks exact
    k_softmax<<<(NND + 255) / 256, 256>>>(b2, out);
}

// round 5
// speedup vs baseline: 1.0845x; 1.0845x over previous
#include <cuda_runtime.h>
#include <cstdint>

#define NND 100000
#define NED 3200000
#define IN_DIM 128
#define HID 64
#define NCLS 8
#define NBLK 391   // ceil(NND/256)

// ---------------- device scratch ----------------
__device__ float g_hproj[(size_t)NND * HID];   // 25.6 MB (L2-resident)
__device__ float g_h2[(size_t)NND * NCLS];     // 3.2 MB
__device__ float g_onorm[NND];
__device__ float g_innorm[NND];
__device__ int   g_outdeg[NND];
__device__ int   g_indeg[NND];
__device__ int   g_csr_src[NED];               // 12.8 MB
__device__ int   g_start[NND];
__device__ int   g_cursor[NND];
__device__ int   g_bsum[512];
__device__ int   g_boff[512];

// ---------------- f32x2 packed math helpers ----------------
__device__ __forceinline__ unsigned long long pk2(float x, float y) {
    unsigned long long r;
    asm("mov.b64 %0, {%1, %2};" : "=l"(r) : "f"(x), "f"(y));
    return r;
}
__device__ __forceinline__ unsigned long long ffma2(unsigned long long a,
                                                    unsigned long long b,
                                                    unsigned long long c) {
    unsigned long long d;
    asm("fma.rn.f32x2 %0, %1, %2, %3;" : "=l"(d) : "l"(a), "l"(b), "l"(c));
    return d;
}

// ---------------- graph preprocessing ----------------
__global__ void k_zero_deg() {
    int i = blockIdx.x * 256 + threadIdx.x;
    if (i < NND) { g_outdeg[i] = 0; g_indeg[i] = 0; }
}

__global__ void k_degree(const int* __restrict__ src, const int* __restrict__ dst) {
    int e = blockIdx.x * 256 + threadIdx.x;   // exact grid
    atomicAdd(&g_outdeg[__ldg(src + e)], 1);
    atomicAdd(&g_indeg[__ldg(dst + e)], 1);
}

// norms + per-block in-degree sums
__global__ void __launch_bounds__(256) k_part1() {
    int b = blockIdx.x, t = threadIdx.x;
    int n = b * 256 + t;
    int deg = 0;
    if (n < NND) {
        int od = g_outdeg[n];
        deg = g_indeg[n];
        g_onorm[n]  = rsqrtf((float)(od  > 1 ? od  : 1));
        g_innorm[n] = rsqrtf((float)(deg > 1 ? deg : 1));
    }
    int v = deg;
    #pragma unroll
    for (int off = 16; off > 0; off >>= 1) v += __shfl_xor_sync(~0u, v, off);
    __shared__ int ssum[8];
    if ((t & 31) == 0) ssum[t >> 5] = v;
    __syncthreads();
    if (t < 8) {
        int w = ssum[t];
        #pragma unroll
        for (int off = 4; off > 0; off >>= 1) w += __shfl_xor_sync(0xffu, w, off);
        if (t == 0) g_bsum[b] = w;
    }
}

__global__ void __launch_bounds__(512) k_scan_bsums() {
    __shared__ int sd[512];
    int t = threadIdx.x;
    int v = (t < NBLK) ? g_bsum[t] : 0;
    sd[t] = v;
    __syncthreads();
    #pragma unroll
    for (int off = 1; off < 512; off <<= 1) {
        int a = sd[t];
        int b = (t >= off) ? sd[t - off] : 0;
        __syncthreads();
        sd[t] = a + b;
        __syncthreads();
    }
    if (t < NBLK) g_boff[t] = sd[t] - v;   // exclusive
}

__global__ void __launch_bounds__(256) k_part2() {
    __shared__ int sd[256];
    int b = blockIdx.x, t = threadIdx.x;
    int n = b * 256 + t;
    int deg = (n < NND) ? g_indeg[n] : 0;
    sd[t] = deg;
    __syncthreads();
    #pragma unroll
    for (int off = 1; off < 256; off <<= 1) {
        int a = sd[t];
        int c = (t >= off) ? sd[t - off] : 0;
        __syncthreads();
        sd[t] = a + c;
        __syncthreads();
    }
    if (n < NND) {
        int start = g_boff[b] + sd[t] - deg;
        g_start[n]  = start;
        g_cursor[n] = start;
    }
}

__global__ void k_fill(const int* __restrict__ src, const int* __restrict__ dst) {
    int e = blockIdx.x * 256 + threadIdx.x;   // exact grid
    int d = __ldg(dst + e);
    int s = __ldg(src + e);
    int pos = atomicAdd(&g_cursor[d], 1);
    g_csr_src[pos] = s;
}

// ---------------- GEMM1: h_proj = (x * out_norm) @ W1 ----------------
// 128 nodes x 64 cols per block, 128 threads, 8x8 per thread via fma.rn.f32x2.
__global__ void __launch_bounds__(128) k_gemm1(const float* __restrict__ x,
                                               const float* __restrict__ W1) {
    __shared__ float xs[32 * 132];   // [k][node], stride 132
    __shared__ float ws[32 * 64];    // [k][col]
    __shared__ float ns[128];

    int t  = threadIdx.x;
    int nb = blockIdx.x * 128;

    ns[t] = (nb + t < NND) ? g_onorm[nb + t] : 0.0f;
    __syncthreads();

    int lr = t & 15, lc = t >> 4;        // loader mapping (store conflict-free)
    int ng = t & 15, cg = t >> 4;        // compute mapping: 8 nodes x 8 cols
    int c4 = ng & 4;                     // read-order swizzle (phase-conflict-free)
    int off_a = ng * 8 + c4;             // holds nodes ng*8 + c4 .. +3
    int off_b = ng * 8 + (c4 ^ 4);

    unsigned long long acc[8][4];
    #pragma unroll
    for (int r = 0; r < 8; r++)
        #pragma unroll
        for (int p = 0; p < 4; p++) acc[r][p] = 0ULL;

    const float4* Wv = (const float4*)W1;

    for (int kc = 0; kc < 4; kc++) {
        #pragma unroll
        for (int i = 0; i < 4; i++)
            ((float4*)ws)[t + 128 * i] = Wv[kc * 512 + t + 128 * i];
        #pragma unroll
        for (int p = 0; p < 8; p++) {
            int row = p * 16 + lr;
            int gn  = nb + row;
            float4 v = make_float4(0.f, 0.f, 0.f, 0.f);
            if (gn < NND)
                v = __ldg((const float4*)(x + (size_t)gn * IN_DIM + kc * 32) + lc);
            float nrm = ns[row];
            int k0 = lc * 4;
            xs[(k0 + 0) * 132 + row] = v.x * nrm;
            xs[(k0 + 1) * 132 + row] = v.y * nrm;
            xs[(k0 + 2) * 132 + row] = v.z * nrm;
            xs[(k0 + 3) * 132 + row] = v.w * nrm;
        }
        __syncthreads();

        #pragma unroll
        for (int k = 0; k < 32; k++) {
            const float* xk = xs + k * 132;
            float4 va = *(const float4*)(xk + off_a);
            float4 vb = *(const float4*)(xk + off_b);
            const float* wk = ws + k * 64 + cg * 8;
            float4 w0 = *(const float4*)wk;
            float4 w1 = *(const float4*)(wk + 4);
            unsigned long long wp0 = pk2(w0.x, w0.y), wp1 = pk2(w0.z, w0.w);
            unsigned long long wp2 = pk2(w1.x, w1.y), wp3 = pk2(w1.z, w1.w);
            float av[8] = {va.x, va.y, va.z, va.w, vb.x, vb.y, vb.z, vb.w};
            #pragma unroll
            for (int r = 0; r < 8; r++) {
                unsigned long long xb = pk2(av[r], av[r]);
                acc[r][0] = ffma2(xb, wp0, acc[r][0]);
                acc[r][1] = ffma2(xb, wp1, acc[r][1]);
                acc[r][2] = ffma2(xb, wp2, acc[r][2]);
                acc[r][3] = ffma2(xb, wp3, acc[r][3]);
            }
        }
        __syncthreads();
    }

    #pragma unroll
    for (int r = 0; r < 8; r++) {
        int node = nb + ng * 8 + ((r < 4) ? c4 : (c4 ^ 4)) + (r & 3);
        if (node < NND) {
            unsigned long long* o =
                (unsigned long long*)(g_hproj + (size_t)node * HID + cg * 8);
            o[0] = acc[r][0]; o[1] = acc[r][1]; o[2] = acc[r][2]; o[3] = acc[r][3];
        }
    }
}

// ---------------- fused aggregate-1 + layer-2 ----------------
// warp per node: pull sum of h_proj[src] rows (float2/lane), then
// relu(agg*innorm + b1)*onorm @ W2 via per-lane W2 rows + warp butterfly.
__global__ void __launch_bounds__(256) k_agg1(const float* __restrict__ W2,
                                              const float* __restrict__ b1) {
    int t = threadIdx.x;
    int lane = t & 31;
    int n = blockIdx.x * 8 + (t >> 5);   // exact: 12500*8 = 100000

    int c0 = lane * 2;
    float4 wa0 = __ldg((const float4*)(W2 + c0 * 8));
    float4 wa1 = __ldg((const float4*)(W2 + c0 * 8 + 4));
    float4 wb0 = __ldg((const float4*)(W2 + c0 * 8 + 8));
    float4 wb1 = __ldg((const float4*)(W2 + c0 * 8 + 12));
    float bb0 = __ldg(b1 + c0);
    float bb1 = __ldg(b1 + c0 + 1);

    int start = g_start[n];
    int deg   = g_indeg[n];
    const float2* hp = (const float2*)g_hproj;

    float a0 = 0.f, a1 = 0.f;
    int i = 0;
    while (i < deg) {
        int cnt = min(32, deg - i);
        int sidx = (lane < cnt) ? __ldg(&g_csr_src[start + i + lane]) : 0;
        int j = 0;
        for (; j + 4 <= cnt; j += 4) {
            int s0 = __shfl_sync(~0u, sidx, j);
            int s1 = __shfl_sync(~0u, sidx, j + 1);
            int s2 = __shfl_sync(~0u, sidx, j + 2);
            int s3 = __shfl_sync(~0u, sidx, j + 3);
            float2 v0 = __ldg(hp + (size_t)s0 * 32 + lane);
            float2 v1 = __ldg(hp + (size_t)s1 * 32 + lane);
            float2 v2 = __ldg(hp + (size_t)s2 * 32 + lane);
            float2 v3 = __ldg(hp + (size_t)s3 * 32 + lane);
            a0 += v0.x; a1 += v0.y;
            a0 += v1.x; a1 += v1.y;
            a0 += v2.x; a1 += v2.y;
            a0 += v3.x; a1 += v3.y;
        }
        for (; j < cnt; j++) {
            int s = __shfl_sync(~0u, sidx, j);
            float2 v = __ldg(hp + (size_t)s * 32 + lane);
            a0 += v.x; a1 += v.y;
        }
        i += cnt;
    }

    float inr = g_innorm[n], onr = g_onorm[n];
    float h0 = fmaxf(fmaf(a0, inr, bb0), 0.f) * onr;
    float h1 = fmaxf(fmaf(a1, inr, bb1), 0.f) * onr;

    float p0 = h0 * wa0.x + h1 * wb0.x;
    float p1 = h0 * wa0.y + h1 * wb0.y;
    float p2 = h0 * wa0.z + h1 * wb0.z;
    float p3 = h0 * wa0.w + h1 * wb0.w;
    float p4 = h0 * wa1.x + h1 * wb1.x;
    float p5 = h0 * wa1.y + h1 * wb1.y;
    float p6 = h0 * wa1.z + h1 * wb1.z;
    float p7 = h0 * wa1.w + h1 * wb1.w;

    #pragma unroll
    for (int off = 16; off > 0; off >>= 1) {
        p0 += __shfl_xor_sync(~0u, p0, off);
        p1 += __shfl_xor_sync(~0u, p1, off);
        p2 += __shfl_xor_sync(~0u, p2, off);
        p3 += __shfl_xor_sync(~0u, p3, off);
        p4 += __shfl_xor_sync(~0u, p4, off);
        p5 += __shfl_xor_sync(~0u, p5, off);
        p6 += __shfl_xor_sync(~0u, p6, off);
        p7 += __shfl_xor_sync(~0u, p7, off);
    }
    if (lane == 0)
        *(float4*)(g_h2 + (size_t)n * NCLS)     = make_float4(p0, p1, p2, p3);
    if (lane == 1)
        *(float4*)(g_h2 + (size_t)n * NCLS + 4) = make_float4(p4, p5, p6, p7);
}

// ---------------- fused aggregate-2 + softmax ----------------
// warp per node; lane = g*8 + j: 4 edges in flight x 8 class-lanes.
__global__ void __launch_bounds__(256) k_agg2(const float* __restrict__ b2,
                                              float* __restrict__ out) {
    int t = threadIdx.x;
    int lane = t & 31;
    int n = blockIdx.x * 8 + (t >> 5);   // exact
    int g = lane >> 3, j = lane & 7;

    int start = g_start[n];
    int deg   = g_indeg[n];

    float acc = 0.f;
    for (int i = 0; i < deg; i += 8) {
        int e0 = i + g, e1 = i + 4 + g;
        if (e0 < deg) {
            int s = __ldg(&g_csr_src[start + e0]);
            acc += __ldg(&g_h2[(size_t)s * NCLS + j]);
        }
        if (e1 < deg) {
            int s = __ldg(&g_csr_src[start + e1]);
            acc += __ldg(&g_h2[(size_t)s * NCLS + j]);
        }
    }
    acc += __shfl_xor_sync(~0u, acc, 8);
    acc += __shfl_xor_sync(~0u, acc, 16);

    float v = fmaf(acc, g_innorm[n], __ldg(b2 + j));
    float m = v;
    m = fmaxf(m, __shfl_xor_sync(~0u, m, 1));
    m = fmaxf(m, __shfl_xor_sync(~0u, m, 2));
    m = fmaxf(m, __shfl_xor_sync(~0u, m, 4));
    float e = __expf(v - m);
    float s = e;
    s += __shfl_xor_sync(~0u, s, 1);
    s += __shfl_xor_sync(~0u, s, 2);
    s += __shfl_xor_sync(~0u, s, 4);
    if (lane < 8) out[(size_t)n * NCLS + lane] = e / s;
}

extern "C" void kernel_launch(void* const* d_in, const int* in_sizes, int n_in,
                              void* d_out, int out_size) {
    const float* x   = (const float*)d_in[0];
    const int*   src = (const int*)  d_in[1];
    const int*   dst = (const int*)  d_in[2];
    const float* W1  = (const float*)d_in[3];
    const float* b1  = (const float*)d_in[4];
    const float* W2  = (const float*)d_in[5];
    const float* b2  = (const float*)d_in[6];
    float* out = (float*)d_out;

    k_zero_deg<<<NBLK, 256>>>();
    k_degree<<<NED / 256, 256>>>(src, dst);
    k_part1<<<NBLK, 256>>>();
    k_scan_bsums<<<1, 512>>>();
    k_part2<<<NBLK, 256>>>();
    k_fill<<<NED / 256, 256>>>(src, dst);
    k_gemm1<<<(NND + 127) / 128, 128>>>(x, W1);
    k_agg1<<<NND / 8, 256>>>(W2, b1);
    k_agg2<<<NND / 8, 256>>>(b2, out);
}

// round 6
// speedup vs baseline: 1.2535x; 1.1558x over previous
#include <cuda_runtime.h>
#include <cuda_fp16.h>
#include <cstdint>

#define NND 100000
#define NED 3200000
#define IN_DIM 128
#define HID 64
#define NCLS 8
#define NBLK 391   // ceil(NND/256)

// ---------------- device scratch ----------------
__device__ __half2 g_hproj[(size_t)NND * 32];  // N x 64 halves = 12.8 MB
__device__ __half2 g_h2[(size_t)NND * 4];      // N x 8 halves  = 1.6 MB
__device__ float g_onorm[NND];
__device__ float g_innorm[NND];
__device__ int   g_outdeg[NND];
__device__ int   g_indeg[NND];
__device__ int   g_csr_src[NED];               // 12.8 MB
__device__ int   g_start[NND];
__device__ int   g_cursor[NND];
__device__ int   g_total;

// ---------------- f32x2 packed math helpers ----------------
__device__ __forceinline__ unsigned long long pk2(float x, float y) {
    unsigned long long r;
    asm("mov.b64 %0, {%1, %2};" : "=l"(r) : "f"(x), "f"(y));
    return r;
}
__device__ __forceinline__ unsigned long long ffma2(unsigned long long a,
                                                    unsigned long long b,
                                                    unsigned long long c) {
    unsigned long long d;
    asm("fma.rn.f32x2 %0, %1, %2, %3;" : "=l"(d) : "l"(a), "l"(b), "l"(c));
    return d;
}
__device__ __forceinline__ float2 unpk2(unsigned long long a) {
    float2 f;
    asm("mov.b64 {%0, %1}, %2;" : "=f"(f.x), "=f"(f.y) : "l"(a));
    return f;
}

// ---------------- launch 1: zero ----------------
__global__ void k_zero() {
    int i = blockIdx.x * 256 + threadIdx.x;
    if (i < NND) { g_outdeg[i] = 0; g_indeg[i] = 0; }
    if (i == 0) g_total = 0;
}

// ---------------- launch 2: degrees ----------------
__global__ void k_degree(const int* __restrict__ src, const int* __restrict__ dst) {
    int e = blockIdx.x * 256 + threadIdx.x;   // exact grid
    atomicAdd(&g_outdeg[__ldg(src + e)], 1);
    atomicAdd(&g_indeg[__ldg(dst + e)], 1);
}

// ---------------- launch 3: norms + CSR start offsets (block-aggregated atomic scan) ----
__global__ void __launch_bounds__(256) k_norm_start() {
    int t = threadIdx.x;
    int n = blockIdx.x * 256 + t;
    int lane = t & 31, w = t >> 5;

    int deg = 0, od = 0;
    if (n < NND) { deg = g_indeg[n]; od = g_outdeg[n]; }

    // warp inclusive scan of deg
    int scan = deg;
    #pragma unroll
    for (int off = 1; off < 32; off <<= 1) {
        int u = __shfl_up_sync(~0u, scan, off);
        if (lane >= off) scan += u;
    }
    __shared__ int wsum[8];
    __shared__ int sbase;
    if (lane == 31) wsum[w] = scan;
    __syncthreads();
    if (t == 0) {
        int tot = 0;
        #pragma unroll
        for (int i = 0; i < 8; i++) { int v = wsum[i]; wsum[i] = tot; tot += v; }
        sbase = atomicAdd(&g_total, tot);
    }
    __syncthreads();

    if (n < NND) {
        g_onorm[n]  = rsqrtf((float)(od  > 1 ? od  : 1));
        g_innorm[n] = rsqrtf((float)(deg > 1 ? deg : 1));
        int start = sbase + wsum[w] + scan - deg;
        g_start[n]  = start;
        g_cursor[n] = start;
    }
}

// ---------------- launch 4 (PROFILED): GEMM1 h_proj = (x*out_norm) @ W1 -> fp16 ----
// 128 nodes x 64 cols per block, 128 threads, 8x8 per thread via fma.rn.f32x2.
__global__ void __launch_bounds__(128) k_gemm1(const float* __restrict__ x,
                                               const float* __restrict__ W1) {
    __shared__ float xs[32 * 132];   // [k][node], stride 132
    __shared__ float ws[32 * 64];    // [k][col]
    __shared__ float ns[128];

    int t  = threadIdx.x;
    int nb = blockIdx.x * 128;

    ns[t] = (nb + t < NND) ? g_onorm[nb + t] : 0.0f;
    __syncthreads();

    int lr = t & 15, lc = t >> 4;        // loader mapping
    int ng = t & 15, cg = t >> 4;        // compute mapping: 8 nodes x 8 cols
    int c4 = ng & 4;                     // phase-conflict-free read swizzle
    int off_a = ng * 8 + c4;
    int off_b = ng * 8 + (c4 ^ 4);

    unsigned long long acc[8][4];
    #pragma unroll
    for (int r = 0; r < 8; r++)
        #pragma unroll
        for (int p = 0; p < 4; p++) acc[r][p] = 0ULL;

    const float4* Wv = (const float4*)W1;

    for (int kc = 0; kc < 4; kc++) {
        #pragma unroll
        for (int i = 0; i < 4; i++)
            ((float4*)ws)[t + 128 * i] = Wv[kc * 512 + t + 128 * i];
        #pragma unroll
        for (int p = 0; p < 8; p++) {
            int row = p * 16 + lr;
            int gn  = nb + row;
            float4 v = make_float4(0.f, 0.f, 0.f, 0.f);
            if (gn < NND)
                v = __ldg((const float4*)(x + (size_t)gn * IN_DIM + kc * 32) + lc);
            float nrm = ns[row];
            int k0 = lc * 4;
            xs[(k0 + 0) * 132 + row] = v.x * nrm;
            xs[(k0 + 1) * 132 + row] = v.y * nrm;
            xs[(k0 + 2) * 132 + row] = v.z * nrm;
            xs[(k0 + 3) * 132 + row] = v.w * nrm;
        }
        __syncthreads();

        #pragma unroll
        for (int k = 0; k < 32; k++) {
            const float* xk = xs + k * 132;
            float4 va = *(const float4*)(xk + off_a);
            float4 vb = *(const float4*)(xk + off_b);
            const float* wk = ws + k * 64 + cg * 8;
            float4 w0 = *(const float4*)wk;
            float4 w1 = *(const float4*)(wk + 4);
            unsigned long long wp0 = pk2(w0.x, w0.y), wp1 = pk2(w0.z, w0.w);
            unsigned long long wp2 = pk2(w1.x, w1.y), wp3 = pk2(w1.z, w1.w);
            float av[8] = {va.x, va.y, va.z, va.w, vb.x, vb.y, vb.z, vb.w};
            #pragma unroll
            for (int r = 0; r < 8; r++) {
                unsigned long long xb = pk2(av[r], av[r]);
                acc[r][0] = ffma2(xb, wp0, acc[r][0]);
                acc[r][1] = ffma2(xb, wp1, acc[r][1]);
                acc[r][2] = ffma2(xb, wp2, acc[r][2]);
                acc[r][3] = ffma2(xb, wp3, acc[r][3]);
            }
        }
        __syncthreads();
    }

    #pragma unroll
    for (int r = 0; r < 8; r++) {
        int node = nb + ng * 8 + ((r < 4) ? c4 : (c4 ^ 4)) + (r & 3);
        if (node < NND) {
            __half2 hh[4];
            #pragma unroll
            for (int p = 0; p < 4; p++) {
                float2 f = unpk2(acc[r][p]);
                hh[p] = __floats2half2_rn(f.x, f.y);
            }
            *(uint4*)(g_hproj + (size_t)node * 32 + cg * 4) = *(uint4*)hh;
        }
    }
}

// ---------------- launch 5: CSR fill ----------------
__global__ void k_fill(const int* __restrict__ src, const int* __restrict__ dst) {
    int e = blockIdx.x * 256 + threadIdx.x;   // exact grid
    int d = __ldg(dst + e);
    int s = __ldg(src + e);
    int pos = atomicAdd(&g_cursor[d], 1);
    g_csr_src[pos] = s;
}

// ---------------- launch 6: fused aggregate-1 + layer-2 -> h2 (fp16) ----------------
// warp per node: pull sum of fp16 h_proj[src] rows (half2/lane, fp32 accum),
// then relu(agg*innorm + b1)*onorm @ W2 via per-lane W2 rows + warp butterfly.
__global__ void __launch_bounds__(256) k_agg1(const float* __restrict__ W2,
                                              const float* __restrict__ b1) {
    int t = threadIdx.x;
    int lane = t & 31;
    int n = blockIdx.x * 8 + (t >> 5);   // exact: 12500*8 = 100000

    int c0 = lane * 2;
    float4 wa0 = __ldg((const float4*)(W2 + c0 * 8));
    float4 wa1 = __ldg((const float4*)(W2 + c0 * 8 + 4));
    float4 wb0 = __ldg((const float4*)(W2 + c0 * 8 + 8));
    float4 wb1 = __ldg((const float4*)(W2 + c0 * 8 + 12));
    float bb0 = __ldg(b1 + c0);
    float bb1 = __ldg(b1 + c0 + 1);

    int start = g_start[n];
    int deg   = g_indeg[n];

    float a0 = 0.f, a1 = 0.f;
    int i = 0;
    while (i < deg) {
        int cnt = min(32, deg - i);
        int sidx = (lane < cnt) ? __ldg(&g_csr_src[start + i + lane]) : 0;
        int j = 0;
        for (; j + 4 <= cnt; j += 4) {
            int s0 = __shfl_sync(~0u, sidx, j);
            int s1 = __shfl_sync(~0u, sidx, j + 1);
            int s2 = __shfl_sync(~0u, sidx, j + 2);
            int s3 = __shfl_sync(~0u, sidx, j + 3);
            float2 v0 = __half22float2(__ldg(g_hproj + (size_t)s0 * 32 + lane));
            float2 v1 = __half22float2(__ldg(g_hproj + (size_t)s1 * 32 + lane));
            float2 v2 = __half22float2(__ldg(g_hproj + (size_t)s2 * 32 + lane));
            float2 v3 = __half22float2(__ldg(g_hproj + (size_t)s3 * 32 + lane));
            a0 += v0.x + v1.x; a1 += v0.y + v1.y;
            a0 += v2.x + v3.x; a1 += v2.y + v3.y;
        }
        for (; j < cnt; j++) {
            int s = __shfl_sync(~0u, sidx, j);
            float2 v = __half22float2(__ldg(g_hproj + (size_t)s * 32 + lane));
            a0 += v.x; a1 += v.y;
        }
        i += cnt;
    }

    float inr = g_innorm[n], onr = g_onorm[n];
    float h0 = fmaxf(fmaf(a0, inr, bb0), 0.f) * onr;
    float h1 = fmaxf(fmaf(a1, inr, bb1), 0.f) * onr;

    float p0 = h0 * wa0.x + h1 * wb0.x;
    float p1 = h0 * wa0.y + h1 * wb0.y;
    float p2 = h0 * wa0.z + h1 * wb0.z;
    float p3 = h0 * wa0.w + h1 * wb0.w;
    float p4 = h0 * wa1.x + h1 * wb1.x;
    float p5 = h0 * wa1.y + h1 * wb1.y;
    float p6 = h0 * wa1.z + h1 * wb1.z;
    float p7 = h0 * wa1.w + h1 * wb1.w;

    #pragma unroll
    for (int off = 16; off > 0; off >>= 1) {
        p0 += __shfl_xor_sync(~0u, p0, off);
        p1 += __shfl_xor_sync(~0u, p1, off);
        p2 += __shfl_xor_sync(~0u, p2, off);
        p3 += __shfl_xor_sync(~0u, p3, off);
        p4 += __shfl_xor_sync(~0u, p4, off);
        p5 += __shfl_xor_sync(~0u, p5, off);
        p6 += __shfl_xor_sync(~0u, p6, off);
        p7 += __shfl_xor_sync(~0u, p7, off);
    }
    if (lane == 0) {
        __half2 hh[4];
        hh[0] = __floats2half2_rn(p0, p1);
        hh[1] = __floats2half2_rn(p2, p3);
        hh[2] = __floats2half2_rn(p4, p5);
        hh[3] = __floats2half2_rn(p6, p7);
        *(uint4*)(g_h2 + (size_t)n * 4) = *(uint4*)hh;
    }
}

// ---------------- launch 7: fused aggregate-2 + softmax ----------------
// warp per node; lane = g*4 + j: 8 edges in flight x 4 class-pair lanes.
__global__ void __launch_bounds__(256) k_agg2(const float* __restrict__ b2,
                                              float* __restrict__ out) {
    int t = threadIdx.x;
    int lane = t & 31;
    int n = blockIdx.x * 8 + (t >> 5);   // exact
    int g = lane >> 2, j = lane & 3;

    int start = g_start[n];
    int deg   = g_indeg[n];

    float ax = 0.f, ay = 0.f;
    for (int i = g; i < deg; i += 8) {
        int s = __ldg(&g_csr_src[start + i]);
        float2 v = __half22float2(__ldg(g_h2 + (size_t)s * 4 + j));
        ax += v.x; ay += v.y;
    }
    // reduce across the 8 edge groups
    #pragma unroll
    for (int off = 4; off < 32; off <<= 1) {
        ax += __shfl_xor_sync(~0u, ax, off);
        ay += __shfl_xor_sync(~0u, ay, off);
    }

    float inr = g_innorm[n];
    float2 bb = __ldg((const float2*)b2 + j);
    float v0 = fmaf(ax, inr, bb.x);
    float v1 = fmaf(ay, inr, bb.y);
    float m = fmaxf(v0, v1);
    m = fmaxf(m, __shfl_xor_sync(~0u, m, 1));
    m = fmaxf(m, __shfl_xor_sync(~0u, m, 2));
    float e0 = __expf(v0 - m), e1 = __expf(v1 - m);
    float s = e0 + e1;
    s += __shfl_xor_sync(~0u, s, 1);
    s += __shfl_xor_sync(~0u, s, 2);
    float rs = 1.0f / s;
    if (g == 0)
        *(float2*)(out + (size_t)n * NCLS + j * 2) = make_float2(e0 * rs, e1 * rs);
}

extern "C" void kernel_launch(void* const* d_in, const int* in_sizes, int n_in,
                              void* d_out, int out_size) {
    const float* x   = (const float*)d_in[0];
    const int*   src = (const int*)  d_in[1];
    const int*   dst = (const int*)  d_in[2];
    const float* W1  = (const float*)d_in[3];
    const float* b1  = (const float*)d_in[4];
    const float* W2  = (const float*)d_in[5];
    const float* b2  = (const float*)d_in[6];
    float* out = (float*)d_out;

    k_zero<<<NBLK, 256>>>();
    k_degree<<<NED / 256, 256>>>(src, dst);
    k_norm_start<<<NBLK, 256>>>();
    k_gemm1<<<(NND + 127) / 128, 128>>>(x, W1);   // launch #4 -> profiled
    k_fill<<<NED / 256, 256>>>(src, dst);
    k_agg1<<<NND / 8, 256>>>(W2, b1);
    k_agg2<<<NND / 8, 256>>>(b2, out);
}

// round 7
// speedup vs baseline: 1.3866x; 1.1062x over previous
#include <cuda_runtime.h>
#include <cuda_fp16.h>
#include <cstdint>

#define NND 100000
#define NED 3200000
#define IN_DIM 128
#define HID 64
#define NCLS 8
#define NBLK 391   // ceil(NND/256)

// ---------------- device scratch ----------------
__device__ __half2 g_hproj[(size_t)NND * 32];  // N x 64 halves = 12.8 MB
__device__ __half2 g_h2[(size_t)NND * 4];      // N x 8 halves  = 1.6 MB
__device__ float g_onorm[NND];
__device__ float g_innorm[NND];
__device__ int   g_outdeg[NND];
__device__ int   g_indeg[NND];
__device__ int   g_csr_src[NED];               // 12.8 MB
__device__ int   g_start[NND];
__device__ int   g_cursor[NND];
__device__ int   g_total;

// ---------------- mma helpers ----------------
__device__ __forceinline__ uint32_t smem_u32(const void* p) {
    return (uint32_t)__cvta_generic_to_shared(p);
}
__device__ __forceinline__ void ldsm_x4(uint32_t addr, uint32_t& r0, uint32_t& r1,
                                        uint32_t& r2, uint32_t& r3) {
    asm volatile("ldmatrix.sync.aligned.m8n8.x4.shared.b16 {%0,%1,%2,%3}, [%4];"
                 : "=r"(r0), "=r"(r1), "=r"(r2), "=r"(r3) : "r"(addr));
}
__device__ __forceinline__ void ldsm_x4_t(uint32_t addr, uint32_t& r0, uint32_t& r1,
                                          uint32_t& r2, uint32_t& r3) {
    asm volatile("ldmatrix.sync.aligned.m8n8.x4.trans.shared.b16 {%0,%1,%2,%3}, [%4];"
                 : "=r"(r0), "=r"(r1), "=r"(r2), "=r"(r3) : "r"(addr));
}
__device__ __forceinline__ void mma_16816(float (&c)[4], uint32_t a0, uint32_t a1,
                                          uint32_t a2, uint32_t a3,
                                          uint32_t b0, uint32_t b1) {
    asm volatile("mma.sync.aligned.m16n8k16.row.col.f32.f16.f16.f32 "
                 "{%0,%1,%2,%3}, {%4,%5,%6,%7}, {%8,%9}, {%0,%1,%2,%3};"
                 : "+f"(c[0]), "+f"(c[1]), "+f"(c[2]), "+f"(c[3])
                 : "r"(a0), "r"(a1), "r"(a2), "r"(a3), "r"(b0), "r"(b1));
}

// ---------------- launch 1: zero ----------------
__global__ void k_zero() {
    int i = blockIdx.x * 256 + threadIdx.x;
    if (i < NND) { g_outdeg[i] = 0; g_indeg[i] = 0; }
    if (i == 0) g_total = 0;
}

// ---------------- launch 2: degrees ----------------
__global__ void k_degree(const int* __restrict__ src, const int* __restrict__ dst) {
    int e = blockIdx.x * 256 + threadIdx.x;   // exact grid
    atomicAdd(&g_outdeg[__ldg(src + e)], 1);
    atomicAdd(&g_indeg[__ldg(dst + e)], 1);
}

// ---------------- launch 3: norms + CSR start offsets ----------------
__global__ void __launch_bounds__(256) k_norm_start() {
    int t = threadIdx.x;
    int n = blockIdx.x * 256 + t;
    int lane = t & 31, w = t >> 5;

    int deg = 0, od = 0;
    if (n < NND) { deg = g_indeg[n]; od = g_outdeg[n]; }

    int scan = deg;
    #pragma unroll
    for (int off = 1; off < 32; off <<= 1) {
        int u = __shfl_up_sync(~0u, scan, off);
        if (lane >= off) scan += u;
    }
    __shared__ int wsum[8];
    __shared__ int sbase;
    if (lane == 31) wsum[w] = scan;
    __syncthreads();
    if (t == 0) {
        int tot = 0;
        #pragma unroll
        for (int i = 0; i < 8; i++) { int v = wsum[i]; wsum[i] = tot; tot += v; }
        sbase = atomicAdd(&g_total, tot);
    }
    __syncthreads();

    if (n < NND) {
        g_onorm[n]  = rsqrtf((float)(od  > 1 ? od  : 1));
        g_innorm[n] = rsqrtf((float)(deg > 1 ? deg : 1));
        int start = sbase + wsum[w] + scan - deg;
        g_start[n]  = start;
        g_cursor[n] = start;
    }
}

// ---------------- launch 4 (PROFILED): GEMM1 via fp16 mma.sync ----------------
// 128 nodes x 64 cols per block, 256 threads / 8 warps; warp w owns m-rows
// [w*16, w*16+16) x all 64 cols. K chunked by 64 (2 chunks, 4 k-steps each).
#define XS_STR 72   // halves per row (64 data + 8 pad) -> 144B, ldmatrix conflict-free
#define WS_STR 72

__global__ void __launch_bounds__(256) k_gemm1(const float* __restrict__ x,
                                               const float* __restrict__ W1) {
    __shared__ __half xs[128 * XS_STR];   // 18432 B
    __shared__ __half ws[64 * WS_STR];    //  9216 B
    __shared__ float  ns[128];

    int t = threadIdx.x;
    int w = t >> 5, lane = t & 31;
    int nb = blockIdx.x * 128;

    if (t < 128) ns[t] = (nb + t < NND) ? g_onorm[nb + t] : 0.0f;
    __syncthreads();

    float acc[8][4] = {};

    uint32_t xbase = smem_u32(xs);
    uint32_t wbase = smem_u32(ws);
    // ldmatrix address lanes
    int arow  = (w << 4) + (lane & 15);        // m-row within tile
    int ahalf = lane >> 4;                     // k half (0/1)
    int brow  = lane & 15;                     // k-row within step
    int bsel  = lane >> 4;                     // which n-tile of the pair

    for (int kc = 0; kc < 2; kc++) {
        // ---- stage x chunk: 128 rows x 64 floats -> fp16*norm ----
        #pragma unroll
        for (int i = 0; i < 8; i++) {
            int li  = i * 256 + t;             // 0..2047
            int row = li >> 4;
            int f4  = li & 15;
            int gn  = nb + row;
            float4 v = (gn < NND)
                ? __ldg((const float4*)(x + (size_t)gn * IN_DIM + kc * 64) + f4)
                : make_float4(0.f, 0.f, 0.f, 0.f);
            float nrm = ns[row];
            __half2 h[2];
            h[0] = __floats2half2_rn(v.x * nrm, v.y * nrm);
            h[1] = __floats2half2_rn(v.z * nrm, v.w * nrm);
            *(uint2*)(xs + row * XS_STR + f4 * 4) = *(uint2*)h;
        }
        // ---- stage W chunk: 64 k-rows x 64 cols -> fp16 ----
        #pragma unroll
        for (int i = 0; i < 4; i++) {
            int li = i * 256 + t;              // 0..1023
            int kr = li >> 4;
            int f4 = li & 15;
            float4 v = __ldg((const float4*)(W1 + (size_t)(kc * 64 + kr) * HID) + f4);
            __half2 h[2];
            h[0] = __floats2half2_rn(v.x, v.y);
            h[1] = __floats2half2_rn(v.z, v.w);
            *(uint2*)(ws + kr * WS_STR + f4 * 4) = *(uint2*)h;
        }
        __syncthreads();

        #pragma unroll
        for (int ks = 0; ks < 4; ks++) {
            uint32_t a0, a1, a2, a3;
            ldsm_x4(xbase + (uint32_t)(arow * (XS_STR * 2) + ks * 32 + ahalf * 16),
                    a0, a1, a2, a3);
            #pragma unroll
            for (int np = 0; np < 4; np++) {   // n-tile pair (2np, 2np+1)
                uint32_t b0, b1, b2, b3;
                uint32_t baddr = wbase
                    + (uint32_t)((ks * 16 + brow) * (WS_STR * 2))
                    + (uint32_t)((np * 2 + bsel) * 16);
                ldsm_x4_t(baddr, b0, b1, b2, b3);
                mma_16816(acc[2 * np],     a0, a1, a2, a3, b0, b1);
                mma_16816(acc[2 * np + 1], a0, a1, a2, a3, b2, b3);
            }
        }
        __syncthreads();
    }

    // ---- epilogue: c0=(g,tg*2) c1=(g,tg*2+1) c2=(g+8,..) -> half2 stores ----
    int g  = lane >> 2, tg = lane & 3;
    int m0 = nb + (w << 4) + g;
    int m1 = m0 + 8;
    #pragma unroll
    for (int nt = 0; nt < 8; nt++) {
        if (m0 < NND)
            g_hproj[(size_t)m0 * 32 + nt * 4 + tg] = __floats2half2_rn(acc[nt][0], acc[nt][1]);
        if (m1 < NND)
            g_hproj[(size_t)m1 * 32 + nt * 4 + tg] = __floats2half2_rn(acc[nt][2], acc[nt][3]);
    }
}

// ---------------- launch 5: CSR fill ----------------
__global__ void k_fill(const int* __restrict__ src, const int* __restrict__ dst) {
    int e = blockIdx.x * 256 + threadIdx.x;   // exact grid
    int d = __ldg(dst + e);
    int s = __ldg(src + e);
    int pos = atomicAdd(&g_cursor[d], 1);
    g_csr_src[pos] = s;
}

// ---------------- launch 6: fused aggregate-1 + layer-2 -> h2 (fp16) ----------------
__global__ void __launch_bounds__(256) k_agg1(const float* __restrict__ W2,
                                              const float* __restrict__ b1) {
    int t = threadIdx.x;
    int lane = t & 31;
    int n = blockIdx.x * 8 + (t >> 5);   // exact: 12500*8 = 100000

    int c0 = lane * 2;
    float4 wa0 = __ldg((const float4*)(W2 + c0 * 8));
    float4 wa1 = __ldg((const float4*)(W2 + c0 * 8 + 4));
    float4 wb0 = __ldg((const float4*)(W2 + c0 * 8 + 8));
    float4 wb1 = __ldg((const float4*)(W2 + c0 * 8 + 12));
    float bb0 = __ldg(b1 + c0);
    float bb1 = __ldg(b1 + c0 + 1);

    int start = g_start[n];
    int deg   = g_indeg[n];

    float a0 = 0.f, a1 = 0.f;
    int i = 0;
    while (i < deg) {
        int cnt = min(32, deg - i);
        int sidx = (lane < cnt) ? __ldg(&g_csr_src[start + i + lane]) : 0;
        int j = 0;
        for (; j + 4 <= cnt; j += 4) {
            int s0 = __shfl_sync(~0u, sidx, j);
            int s1 = __shfl_sync(~0u, sidx, j + 1);
            int s2 = __shfl_sync(~0u, sidx, j + 2);
            int s3 = __shfl_sync(~0u, sidx, j + 3);
            float2 v0 = __half22float2(__ldg(g_hproj + (size_t)s0 * 32 + lane));
            float2 v1 = __half22float2(__ldg(g_hproj + (size_t)s1 * 32 + lane));
            float2 v2 = __half22float2(__ldg(g_hproj + (size_t)s2 * 32 + lane));
            float2 v3 = __half22float2(__ldg(g_hproj + (size_t)s3 * 32 + lane));
            a0 += v0.x + v1.x; a1 += v0.y + v1.y;
            a0 += v2.x + v3.x; a1 += v2.y + v3.y;
        }
        for (; j < cnt; j++) {
            int s = __shfl_sync(~0u, sidx, j);
            float2 v = __half22float2(__ldg(g_hproj + (size_t)s * 32 + lane));
            a0 += v.x; a1 += v.y;
        }
        i += cnt;
    }

    float inr = g_innorm[n], onr = g_onorm[n];
    float h0 = fmaxf(fmaf(a0, inr, bb0), 0.f) * onr;
    float h1 = fmaxf(fmaf(a1, inr, bb1), 0.f) * onr;

    float p0 = h0 * wa0.x + h1 * wb0.x;
    float p1 = h0 * wa0.y + h1 * wb0.y;
    float p2 = h0 * wa0.z + h1 * wb0.z;
    float p3 = h0 * wa0.w + h1 * wb0.w;
    float p4 = h0 * wa1.x + h1 * wb1.x;
    float p5 = h0 * wa1.y + h1 * wb1.y;
    float p6 = h0 * wa1.z + h1 * wb1.z;
    float p7 = h0 * wa1.w + h1 * wb1.w;

    #pragma unroll
    for (int off = 16; off > 0; off >>= 1) {
        p0 += __shfl_xor_sync(~0u, p0, off);
        p1 += __shfl_xor_sync(~0u, p1, off);
        p2 += __shfl_xor_sync(~0u, p2, off);
        p3 += __shfl_xor_sync(~0u, p3, off);
        p4 += __shfl_xor_sync(~0u, p4, off);
        p5 += __shfl_xor_sync(~0u, p5, off);
        p6 += __shfl_xor_sync(~0u, p6, off);
        p7 += __shfl_xor_sync(~0u, p7, off);
    }
    if (lane == 0) {
        __half2 hh[4];
        hh[0] = __floats2half2_rn(p0, p1);
        hh[1] = __floats2half2_rn(p2, p3);
        hh[2] = __floats2half2_rn(p4, p5);
        hh[3] = __floats2half2_rn(p6, p7);
        *(uint4*)(g_h2 + (size_t)n * 4) = *(uint4*)hh;
    }
}

// ---------------- launch 7: fused aggregate-2 + softmax ----------------
__global__ void __launch_bounds__(256) k_agg2(const float* __restrict__ b2,
                                              float* __restrict__ out) {
    int t = threadIdx.x;
    int lane = t & 31;
    int n = blockIdx.x * 8 + (t >> 5);   // exact
    int g = lane >> 2, j = lane & 3;

    int start = g_start[n];
    int deg   = g_indeg[n];

    float ax = 0.f, ay = 0.f;
    for (int i = g; i < deg; i += 8) {
        int s = __ldg(&g_csr_src[start + i]);
        float2 v = __half22float2(__ldg(g_h2 + (size_t)s * 4 + j));
        ax += v.x; ay += v.y;
    }
    #pragma unroll
    for (int off = 4; off < 32; off <<= 1) {
        ax += __shfl_xor_sync(~0u, ax, off);
        ay += __shfl_xor_sync(~0u, ay, off);
    }

    float inr = g_innorm[n];
    float2 bb = __ldg((const float2*)b2 + j);
    float v0 = fmaf(ax, inr, bb.x);
    float v1 = fmaf(ay, inr, bb.y);
    float m = fmaxf(v0, v1);
    m = fmaxf(m, __shfl_xor_sync(~0u, m, 1));
    m = fmaxf(m, __shfl_xor_sync(~0u, m, 2));
    float e0 = __expf(v0 - m), e1 = __expf(v1 - m);
    float s = e0 + e1;
    s += __shfl_xor_sync(~0u, s, 1);
    s += __shfl_xor_sync(~0u, s, 2);
    float rs = 1.0f / s;
    if (g == 0)
        *(float2*)(out + (size_t)n * NCLS + j * 2) = make_float2(e0 * rs, e1 * rs);
}

extern "C" void kernel_launch(void* const* d_in, const int* in_sizes, int n_in,
                              void* d_out, int out_size) {
    const float* x   = (const float*)d_in[0];
    const int*   src = (const int*)  d_in[1];
    const int*   dst = (const int*)  d_in[2];
    const float* W1  = (const float*)d_in[3];
    const float* b1  = (const float*)d_in[4];
    const float* W2  = (const float*)d_in[5];
    const float* b2  = (const float*)d_in[6];
    float* out = (float*)d_out;

    k_zero<<<NBLK, 256>>>();
    k_degree<<<NED / 256, 256>>>(src, dst);
    k_norm_start<<<NBLK, 256>>>();
    k_gemm1<<<(NND + 127) / 128, 256>>>(x, W1);   // launch #4 -> profiled
    k_fill<<<NED / 256, 256>>>(src, dst);
    k_agg1<<<NND / 8, 256>>>(W2, b1);
    k_agg2<<<NND / 8, 256>>>(b2, out);
}